// round 10
// baseline (speedup 1.0000x reference)
#include <cuda_runtime.h>

#define B_  256
#define T_  2048
#define H_  64
#define O_  2
#define NROWS (B_ * T_)
#define PF  4   // fused-scan xin prefetch depth (T_ % PF == 0)
#define STG 4   // gemm cp.async pipeline depth

// Scratch (device globals — no allocation allowed in kernel_launch)
__device__ float g_bufA[NROWS * H_];
__device__ float g_bufB[NROWS * H_];

// ---------- packed f32x2 helpers (sm_103a FFMA2 path) ----------
static __device__ __forceinline__ unsigned long long pack2(float lo, float hi) {
    unsigned long long r;
    asm("mov.b64 %0, {%1, %2};" : "=l"(r) : "f"(lo), "f"(hi));
    return r;
}
static __device__ __forceinline__ void unpack2(unsigned long long v, float& a, float& b) {
    asm("mov.b64 {%0, %1}, %2;" : "=f"(a), "=f"(b) : "l"(v));
}
static __device__ __forceinline__ unsigned long long fma2(unsigned long long a,
                                                          unsigned long long b,
                                                          unsigned long long c) {
    unsigned long long d;
    asm("fma.rn.f32x2 %0, %1, %2, %3;" : "=l"(d) : "l"(a), "l"(b), "l"(c));
    return d;
}
static __device__ __forceinline__ unsigned long long add2(unsigned long long a,
                                                          unsigned long long b) {
    unsigned long long d;
    asm("add.rn.f32x2 %0, %1, %2;" : "=l"(d) : "l"(a), "l"(b));
    return d;
}

// Fast tanh, rel err ~1e-7, saturates correctly.
static __device__ __forceinline__ float fast_tanh(float x) {
    float e = __expf(2.0f * x);
    return 1.0f - __fdividef(2.0f, e + 1.0f);
}

static __device__ __forceinline__ unsigned smem_u32(const void* p) {
    unsigned r;
    asm("{ .reg .u64 t; cvta.to.shared.u64 t, %1; cvt.u32.u64 %0, t; }"
        : "=r"(r) : "l"(p));
    return r;
}

#define NAMED_BAR(id, cnt)    asm volatile("bar.sync %0, %1;"   :: "r"(id), "r"(cnt) : "memory")
#define NAMED_ARRIVE(id, cnt) asm volatile("bar.arrive %0, %1;" :: "r"(id), "r"(cnt) : "memory")
#define CP_COMMIT()           asm volatile("cp.async.commit_group;" ::: "memory")
#define CP_WAIT(n)            asm volatile("cp.async.wait_group %0;" :: "n"(n) : "memory")

// guarded 16B cp.async (skipped when row OOB; empty issue is fine)
static __device__ __forceinline__ void cp16_guard(unsigned dst, const float* src, bool ok) {
    if (ok)
        asm volatile("cp.async.cg.shared.global [%0], [%1], 16;"
                     :: "r"(dst), "l"(src) : "memory");
}

// ============================================================================
// gemm64 (cp.async pipelined, 4 rows/iter):
// out[r][j] = sum_k in[r][k]*W[j][k] + ba[j] + bb[j]
// x rows staged by LDGSTS into a per-warp 4-stage smem ring -> 3-4 KB of
// in-flight DRAM reads per warp WITHOUT register cost. Weights in regs.
// ============================================================================
__global__ void __launch_bounds__(128) gemm64_kernel(
    const float* __restrict__ in, const float* __restrict__ W,
    const float* __restrict__ ba, const float* __restrict__ bb,
    float* __restrict__ out, int nrows)
{
    __shared__ __align__(16) unsigned long long xsm[4][STG][4][32]; // [warp][stage][row][pair]
    const int l   = threadIdx.x & 31;
    const int wrp = threadIdx.x >> 5;
    const unsigned long long* Wu = (const unsigned long long*)W;

    unsigned long long wl[32], wh[32];
#pragma unroll
    for (int k = 0; k < 32; k++) {
        wl[k] = Wu[l * 32 + k];
        wh[k] = Wu[(l + 32) * 32 + k];
    }
    const float biasl = ba[l] + bb[l];
    const float biash = ba[l + 32] + bb[l + 32];

    const int  warpId = blockIdx.x * 4 + wrp;
    const int  nw     = gridDim.x * 4;
    const long stride = 4L * nw;

    // each lane fetches two 16B chunks per stage: rows (l>>4) and (l>>4)+2
    const int rA   = l >> 4;       // 0..1
    const int c16  = l & 15;       // 16B-chunk within row
    const unsigned sbase = smem_u32(&xsm[wrp][0][0][0]);

    const long r0 = 4L * warpId;
    if (r0 >= nrows) { /* still must not hang: no block-wide sync used */ return; }

    // prologue: fill all stages
#pragma unroll
    for (int s = 0; s < STG; s++) {
        const long rb = r0 + (long)s * stride;
        const unsigned d0 = sbase + s * 1024 + rA * 256 + c16 * 16;
        cp16_guard(d0,       in + (rb + rA)     * 64 + c16 * 4, rb + rA     < nrows);
        cp16_guard(d0 + 512, in + (rb + rA + 2) * 64 + c16 * 4, rb + rA + 2 < nrows);
        CP_COMMIT();
    }

    long r = r0;
    int slot = 0;
    while (r < nrows) {
        CP_WAIT(STG - 1);
        __syncwarp();

        unsigned long long aL[4], aH[4], bL[4], bH[4];
#pragma unroll
        for (int q = 0; q < 4; q++) {
            aL[q] = pack2(biasl, 0.f); bL[q] = 0ull;
            aH[q] = pack2(biash, 0.f); bH[q] = 0ull;
        }
#pragma unroll
        for (int k = 0; k < 32; k += 2) {
#pragma unroll
            for (int q = 0; q < 4; q++) {
                ulonglong2 v = ((const ulonglong2*)&xsm[wrp][slot][q][0])[k >> 1];
                aL[q] = fma2(wl[k],     v.x, aL[q]);
                bL[q] = fma2(wl[k + 1], v.y, bL[q]);
                aH[q] = fma2(wh[k],     v.x, aH[q]);
                bH[q] = fma2(wh[k + 1], v.y, bH[q]);
            }
        }

        // refill this slot for iteration r + STG*stride (issued AFTER the
        // LDS reads above; arrival is >=300cyc away, LDS done in ~30)
        {
            const long rn = r + (long)STG * stride;
            const unsigned d0 = sbase + slot * 1024 + rA * 256 + c16 * 16;
            cp16_guard(d0,       in + (rn + rA)     * 64 + c16 * 4, rn + rA     < nrows);
            cp16_guard(d0 + 512, in + (rn + rA + 2) * 64 + c16 * 4, rn + rA + 2 < nrows);
            CP_COMMIT();   // commit even when empty: keeps group accounting fixed
        }

#pragma unroll
        for (int q = 0; q < 4; q++) {
            if (r + q < nrows) {
                float s0, s1, t0, t1;
                unpack2(add2(aL[q], bL[q]), s0, s1);
                unpack2(add2(aH[q], bH[q]), t0, t1);
                out[(r + q) * 64 + l]      = s0 + s1;
                out[(r + q) * 64 + 32 + l] = t0 + t1;
            }
        }

        r += stride;
        slot = (slot + 1) & (STG - 1);
    }
}

// ============================================================================
// fused_scan + MLP-W1 (arrive/sync split barrier):
//   h0_i     = tanh(x_i + W_hh0 h0_{i-1})
//   h1_{i-1} = tanh(W_ih1 h0_{i-1} + b1rnn + W_hh1 h1_{i-2})
//   z_{i-2}  = relu(W1 h1_{i-2} + b1mlp)
// Block = 256 thr = 2 batches x 4 warps; per-batch named barrier.
// Each step: STS h -> bar.arrive -> (z STG + xin LDG in the gap) -> bar.sync.
// Count = 256 = 128 threads x (1 arrive + 1 sync-arrive).
// ============================================================================
__global__ void __launch_bounds__(256) fused_scan_kernel(
    const float* __restrict__ xin0,
    const float* __restrict__ Whh0, const float* __restrict__ Wih1,
    const float* __restrict__ Whh1,
    const float* __restrict__ b_ih1, const float* __restrict__ b_hh1,
    const float* __restrict__ W1,   const float* __restrict__ b1,
    float* __restrict__ zout)
{
    __shared__ __align__(16) float h0sm[2][2][64];
    __shared__ __align__(16) float h1sm[2][2][64];
    const int l     = threadIdx.x & 31;
    const int wid   = threadIdx.x >> 5;
    const int bl    = wid >> 2;            // batch slot (0..1)
    const int wq    = wid & 3;             // warp-in-batch
    const int j     = wq * 16 + (l & 15);  // owned output
    const int kh    = l >> 4;              // K-half
    const bool lead = (l < 16);
    const long b    = blockIdx.x * 2 + bl;
    const int barid = bl + 1;

    const unsigned long long* W0u = (const unsigned long long*)Whh0;
    const unsigned long long* Wxu = (const unsigned long long*)Wih1;
    const unsigned long long* W1u = (const unsigned long long*)Whh1;
    const unsigned long long* Wmu = (const unsigned long long*)W1;
    unsigned long long w0[16], wx[16], w1[16], wm[16];
#pragma unroll
    for (int m = 0; m < 16; m++) {
        const int k = kh * 16 + m;
        w0[m] = W0u[j * 32 + k];
        wx[m] = Wxu[j * 32 + k];
        w1[m] = W1u[j * 32 + k];
        wm[m] = Wmu[j * 32 + k];
    }
    const float bias1g = lead ? (b_ih1[j] + b_hh1[j]) : 0.f;
    const float b1m    = lead ? b1[j] : 0.f;

    if (lead) {
        h0sm[bl][0][j] = 0.f;   // h0_{-1}
        h1sm[bl][0][j] = 0.f;   // h1_{-2}
    }

    const float* xb = xin0 + b * T_ * 64;
    float*       zb = zout + b * T_ * 64;

    float xs[PF];
#pragma unroll
    for (int s = 0; s < PF; s++) xs[s] = xb[s * 64 + j];

    NAMED_BAR(barid, 128);

    int p = 0;
    for (int tb = 0; tb < T_; tb += PF) {
#pragma unroll
        for (int u = 0; u < PF; u++) {
            const int i = tb + u;
            const float xv = lead ? xs[u] : 0.f;

            // h0sm[bl][p] = h0_{i-1}, h1sm[bl][p] = h1_{i-2}
            unsigned long long a0 = pack2(xv, 0.f), a1 = 0ull;       // Whh0.h0
            unsigned long long c0 = pack2(bias1g, 0.f), c1 = 0ull;   // Wih1.h0
            unsigned long long d0 = 0ull, d1 = 0ull;                 // Whh1.h1
            unsigned long long m0 = pack2(b1m, 0.f), m1 = 0ull;      // W1.h1
            const ulonglong2* hp0 = (const ulonglong2*)&h0sm[bl][p][kh * 32];
            const ulonglong2* hp1 = (const ulonglong2*)&h1sm[bl][p][kh * 32];
#pragma unroll
            for (int m = 0; m < 16; m += 2) {
                ulonglong2 v = hp0[m >> 1];   // h0_{i-1}
                ulonglong2 g = hp1[m >> 1];   // h1_{i-2}
                a0 = fma2(w0[m],     v.x, a0);
                a1 = fma2(w0[m + 1], v.y, a1);
                c0 = fma2(wx[m],     v.x, c0);
                c1 = fma2(wx[m + 1], v.y, c1);
                d0 = fma2(w1[m],     g.x, d0);
                d1 = fma2(w1[m + 1], g.y, d1);
                m0 = fma2(wm[m],     g.x, m0);
                m1 = fma2(wm[m + 1], g.y, m1);
            }
            float s0, s1, e0, e1, z0, z1;
            unpack2(add2(a0, a1), s0, s1);
            unpack2(add2(add2(c0, c1), add2(d0, d1)), e0, e1);
            unpack2(add2(m0, m1), z0, z1);
            float sh = s0 + s1;
            float eh = e0 + e1;
            float zh = z0 + z1;
            sh += __shfl_xor_sync(0xffffffffu, sh, 16);
            eh += __shfl_xor_sync(0xffffffffu, eh, 16);
            zh += __shfl_xor_sync(0xffffffffu, zh, 16);

            const float h0v = fast_tanh(sh);
            float h1v = fast_tanh(eh);          // = h1_{i-1}
            if (i == 0) h1v = 0.f;              // h1_{-1} := 0
            const float zv = fmaxf(zh, 0.f);    // = z_{i-2}

            if (lead) {
                h0sm[bl][p ^ 1][j] = h0v;
                h1sm[bl][p ^ 1][j] = h1v;
            }
            NAMED_ARRIVE(barid, 256);

            // ---- gap work: global traffic off the critical path ----
            if (lead && i >= 2) zb[(i - 2) * 64 + j] = zv;
            if (i + PF < T_)    xs[u] = xb[(i + PF) * 64 + j];

            NAMED_BAR(barid, 256);
            p ^= 1;
        }
    }

    // Epilogue step 1: h1_{T-1} and z_{T-2}
    {
        unsigned long long c0 = pack2(bias1g, 0.f), c1 = 0ull;
        unsigned long long d0 = 0ull, d1 = 0ull;
        unsigned long long m0 = pack2(b1m, 0.f), m1 = 0ull;
        const ulonglong2* hp0 = (const ulonglong2*)&h0sm[bl][p][kh * 32];
        const ulonglong2* hp1 = (const ulonglong2*)&h1sm[bl][p][kh * 32];
#pragma unroll
        for (int m = 0; m < 16; m += 2) {
            ulonglong2 v = hp0[m >> 1];   // h0_{T-1}
            ulonglong2 g = hp1[m >> 1];   // h1_{T-2}
            c0 = fma2(wx[m],     v.x, c0);
            c1 = fma2(wx[m + 1], v.y, c1);
            d0 = fma2(w1[m],     g.x, d0);
            d1 = fma2(w1[m + 1], g.y, d1);
            m0 = fma2(wm[m],     g.x, m0);
            m1 = fma2(wm[m + 1], g.y, m1);
        }
        float e0, e1, z0, z1;
        unpack2(add2(add2(c0, c1), add2(d0, d1)), e0, e1);
        unpack2(add2(m0, m1), z0, z1);
        float eh = e0 + e1;
        float zh = z0 + z1;
        eh += __shfl_xor_sync(0xffffffffu, eh, 16);
        zh += __shfl_xor_sync(0xffffffffu, zh, 16);
        if (lead) {
            zb[(T_ - 2) * 64 + j] = fmaxf(zh, 0.f);
            h1sm[bl][p ^ 1][j] = fast_tanh(eh);   // h1_{T-1}
        }
        NAMED_BAR(barid, 128);
    }
    // Epilogue step 2: z_{T-1} = relu(W1 h1_{T-1} + b1)
    {
        unsigned long long m0 = pack2(b1m, 0.f), m1 = 0ull;
        const ulonglong2* hp1 = (const ulonglong2*)&h1sm[bl][p ^ 1][kh * 32];
#pragma unroll
        for (int m = 0; m < 16; m += 2) {
            ulonglong2 g = hp1[m >> 1];
            m0 = fma2(wm[m],     g.x, m0);
            m1 = fma2(wm[m + 1], g.y, m1);
        }
        float z0, z1;
        unpack2(add2(m0, m1), z0, z1);
        float zh = z0 + z1;
        zh += __shfl_xor_sync(0xffffffffu, zh, 16);
        if (lead) zb[(T_ - 1) * 64 + j] = fmaxf(zh, 0.f);
    }
}

// ============================================================================
// w2: out[r][o] = sum_j W2[o][j] z[r][j] + b2[o]  (O=2). 8 rows/iter (MLP).
// ============================================================================
__global__ void __launch_bounds__(128) w2_kernel(
    const float* __restrict__ z, const float* __restrict__ W2,
    const float* __restrict__ b2, float* __restrict__ out, int nrows)
{
    const int l = threadIdx.x & 31;
    const int wrp = threadIdx.x >> 5;
    const unsigned long long* Zu  = (const unsigned long long*)z;
    const unsigned long long* W2u = (const unsigned long long*)W2;

    const unsigned long long w2a = W2u[l];        // (W2[0][2l], W2[0][2l+1])
    const unsigned long long w2b = W2u[32 + l];   // (W2[1][2l], W2[1][2l+1])
    const float b20 = b2[0], b21 = b2[1];

    const int  warpId = blockIdx.x * 4 + wrp;
    const int  nw     = gridDim.x * 4;
    const long stride = 8L * nw;

    for (long r = 8L * warpId; r < nrows; r += stride) {
        unsigned long long zv[8];
#pragma unroll
        for (int q = 0; q < 8; q++)
            zv[q] = (r + q < nrows) ? Zu[(r + q) * 32 + l] : 0ull;

        float p0[8], p1[8];
#pragma unroll
        for (int q = 0; q < 8; q++) {
            float a0, a1, c0, c1;
            unpack2(fma2(w2a, zv[q], 0ull), a0, a1);
            unpack2(fma2(w2b, zv[q], 0ull), c0, c1);
            p0[q] = a0 + a1;
            p1[q] = c0 + c1;
        }
#pragma unroll
        for (int off = 16; off; off >>= 1) {
#pragma unroll
            for (int q = 0; q < 8; q++) {
                p0[q] += __shfl_xor_sync(0xffffffffu, p0[q], off);
                p1[q] += __shfl_xor_sync(0xffffffffu, p1[q], off);
            }
        }
        if (l == 0) {
#pragma unroll
            for (int q = 0; q < 8; q++)
                if (r + q < nrows)
                    *reinterpret_cast<float2*>(&out[(r + q) * 2]) =
                        make_float2(p0[q] + b20, p1[q] + b21);
        }
    }
}

// ============================================================================
extern "C" void kernel_launch(void* const* d_in, const int* in_sizes, int n_in,
                              void* d_out, int out_size)
{
    const float* x     = (const float*)d_in[0];
    const float* W_ih0 = (const float*)d_in[1];
    const float* W_hh0 = (const float*)d_in[2];
    const float* b_ih0 = (const float*)d_in[3];
    const float* b_hh0 = (const float*)d_in[4];
    const float* W_ih1 = (const float*)d_in[5];
    const float* W_hh1 = (const float*)d_in[6];
    const float* b_ih1 = (const float*)d_in[7];
    const float* b_hh1 = (const float*)d_in[8];
    const float* W1    = (const float*)d_in[9];
    const float* b1    = (const float*)d_in[10];
    const float* W2    = (const float*)d_in[11];
    const float* b2    = (const float*)d_in[12];
    float* out = (float*)d_out;

    static float* bufA = nullptr;
    static float* bufB = nullptr;
    if (!bufA) {
        cudaGetSymbolAddress((void**)&bufA, g_bufA);
        cudaGetSymbolAddress((void**)&bufB, g_bufB);
    }

    // xin0 = x W_ih0^T + b_ih0 + b_hh0
    gemm64_kernel<<<1184, 128>>>(x, W_ih0, b_ih0, b_hh0, bufA, NROWS);
    // both RNN layers + MLP W1 -> z
    fused_scan_kernel<<<B_ / 2, 256>>>(bufA, W_hh0, W_ih1, W_hh1,
                                       b_ih1, b_hh1, W1, b1, bufB);
    // out = z W2^T + b2
    w2_kernel<<<1024, 128>>>(bufB, W2, b2, out, NROWS);
}

// round 11
// speedup vs baseline: 1.2387x; 1.2387x over previous
#include <cuda_runtime.h>

#define B_  256
#define T_  2048
#define H_  64
#define O_  2
#define NROWS (B_ * T_)
#define PF  4    // step unroll (T_ % PF == 0)

// Scratch (device global — no allocation allowed in kernel_launch)
__device__ float g_bufB[NROWS * H_];

// ---------- packed f32x2 helpers (sm_103a FFMA2 path) ----------
static __device__ __forceinline__ unsigned long long pack2(float lo, float hi) {
    unsigned long long r;
    asm("mov.b64 %0, {%1, %2};" : "=l"(r) : "f"(lo), "f"(hi));
    return r;
}
static __device__ __forceinline__ void unpack2(unsigned long long v, float& a, float& b) {
    asm("mov.b64 {%0, %1}, %2;" : "=f"(a), "=f"(b) : "l"(v));
}
static __device__ __forceinline__ unsigned long long fma2(unsigned long long a,
                                                          unsigned long long b,
                                                          unsigned long long c) {
    unsigned long long d;
    asm("fma.rn.f32x2 %0, %1, %2, %3;" : "=l"(d) : "l"(a), "l"(b), "l"(c));
    return d;
}
static __device__ __forceinline__ unsigned long long add2(unsigned long long a,
                                                          unsigned long long b) {
    unsigned long long d;
    asm("add.rn.f32x2 %0, %1, %2;" : "=l"(d) : "l"(a), "l"(b));
    return d;
}

// Fast tanh, rel err ~1e-7, saturates correctly.
static __device__ __forceinline__ float fast_tanh(float x) {
    float e = __expf(2.0f * x);
    return 1.0f - __fdividef(2.0f, e + 1.0f);
}

#define NAMED_BAR(id, cnt) asm volatile("bar.sync %0, %1;" :: "r"(id), "r"(cnt) : "memory")

// ============================================================================
// fused_scan (everything but W2): iteration i computes, CONCURRENTLY,
//   xin0_i   = W_ih0 x_i + b_ih0 + b_hh0        <- GEMM fused in (issue slack)
//   h0_i     = tanh(xin0_i + W_hh0 h0_{i-1})
//   h1_{i-1} = tanh(W_ih1 h0_{i-1} + b1rnn + W_hh1 h1_{i-2})
//   z_{i-2}  = relu(W1 h1_{i-2} + b1mlp)
// x streamed through a 16-slot smem ring per batch:
//   step i: consume slot i&15 (x_i); STS x_{i+8} (reg) -> slot (i+8)&15
//   (its old readers finished 8 barriers ago); LDG x_{i+12} -> reg (4-step
//   latency cover). Prologue fills slots 0..7 and regs x_8..x_11.
// Block = 256 thr = 2 batches x 4 warps; per-batch named barrier (R9 org).
// Lane owns output j = wq*16+(l&15), K-half kh=l>>4; halves via shfl_xor(16).
// ============================================================================
__global__ void __launch_bounds__(256) fused_scan_kernel(
    const float* __restrict__ x,
    const float* __restrict__ Wih0, const float* __restrict__ Whh0,
    const float* __restrict__ b_ih0, const float* __restrict__ b_hh0,
    const float* __restrict__ Wih1, const float* __restrict__ Whh1,
    const float* __restrict__ b_ih1, const float* __restrict__ b_hh1,
    const float* __restrict__ W1,   const float* __restrict__ b1,
    float* __restrict__ zout)
{
    __shared__ __align__(16) float h0sm[2][2][64];
    __shared__ __align__(16) float h1sm[2][2][64];
    __shared__ __align__(16) float xsm[2][16][64];   // x ring
    const int l     = threadIdx.x & 31;
    const int wid   = threadIdx.x >> 5;
    const int bl    = wid >> 2;            // batch slot (0..1)
    const int wq    = wid & 3;             // warp-in-batch
    const int j     = wq * 16 + (l & 15);  // owned output
    const int kh    = l >> 4;              // K-half
    const bool lead = (l < 16);
    const long b    = blockIdx.x * 2 + bl;
    const int barid = bl + 1;

    const unsigned long long* Wiu = (const unsigned long long*)Wih0;
    const unsigned long long* W0u = (const unsigned long long*)Whh0;
    const unsigned long long* Wxu = (const unsigned long long*)Wih1;
    const unsigned long long* W1u = (const unsigned long long*)Whh1;
    const unsigned long long* Wmu = (const unsigned long long*)W1;
    unsigned long long wi[16], w0[16], wx[16], w1[16], wm[16];
#pragma unroll
    for (int m = 0; m < 16; m++) {
        const int k = kh * 16 + m;
        wi[m] = Wiu[j * 32 + k];
        w0[m] = W0u[j * 32 + k];
        wx[m] = Wxu[j * 32 + k];
        w1[m] = W1u[j * 32 + k];
        wm[m] = Wmu[j * 32 + k];
    }
    const float bias0g = lead ? (b_ih0[j] + b_hh0[j]) : 0.f;  // layer-0 bias
    const float bias1g = lead ? (b_ih1[j] + b_hh1[j]) : 0.f;  // layer-1 bias
    const float b1m    = lead ? b1[j] : 0.f;                  // MLP W1 bias

    if (lead) {
        h0sm[bl][0][j] = 0.f;   // h0_{-1}
        h1sm[bl][0][j] = 0.f;   // h1_{-2}
    }

    const float* xb = x    + b * T_ * 64;
    float*       zb = zout + b * T_ * 64;

    // prologue: x ring slots 0..7, regs x_8..x_11
    float xreg[PF];
    if (lead) {
#pragma unroll
        for (int s = 0; s < 8; s++) xsm[bl][s][j] = xb[s * 64 + j];
#pragma unroll
        for (int u = 0; u < PF; u++) xreg[u] = xb[(8 + u) * 64 + j];
    }

    NAMED_BAR(barid, 128);

    int p = 0;
    for (int tb = 0; tb < T_; tb += PF) {
#pragma unroll
        for (int u = 0; u < PF; u++) {
            const int i = tb + u;

            // h0sm[bl][p] = h0_{i-1}, h1sm[bl][p] = h1_{i-2}, x ring slot i&15 = x_i
            unsigned long long ax0 = 0ull, ax1 = 0ull;               // Wih0.x_i
            unsigned long long a0 = pack2(bias0g, 0.f), a1 = 0ull;   // Whh0.h0
            unsigned long long c0 = pack2(bias1g, 0.f), c1 = 0ull;   // Wih1.h0
            unsigned long long d0 = 0ull, d1 = 0ull;                 // Whh1.h1
            unsigned long long m0 = pack2(b1m, 0.f), m1 = 0ull;      // W1.h1
            const ulonglong2* xp  = (const ulonglong2*)&xsm[bl][i & 15][kh * 32];
            const ulonglong2* hp0 = (const ulonglong2*)&h0sm[bl][p][kh * 32];
            const ulonglong2* hp1 = (const ulonglong2*)&h1sm[bl][p][kh * 32];
#pragma unroll
            for (int m = 0; m < 16; m += 2) {
                ulonglong2 xv = xp[m >> 1];   // x_i
                ulonglong2 v  = hp0[m >> 1];  // h0_{i-1}
                ulonglong2 g  = hp1[m >> 1];  // h1_{i-2}
                ax0 = fma2(wi[m],     xv.x, ax0);
                ax1 = fma2(wi[m + 1], xv.y, ax1);
                a0  = fma2(w0[m],     v.x,  a0);
                a1  = fma2(w0[m + 1], v.y,  a1);
                c0  = fma2(wx[m],     v.x,  c0);
                c1  = fma2(wx[m + 1], v.y,  c1);
                d0  = fma2(w1[m],     g.x,  d0);
                d1  = fma2(w1[m + 1], g.y,  d1);
                m0  = fma2(wm[m],     g.x,  m0);
                m1  = fma2(wm[m + 1], g.y,  m1);
            }
            float s0, s1, e0, e1, z0, z1;
            unpack2(add2(add2(a0, a1), add2(ax0, ax1)), s0, s1);
            unpack2(add2(add2(c0, c1), add2(d0, d1)), e0, e1);
            unpack2(add2(m0, m1), z0, z1);
            float sh = s0 + s1;
            float eh = e0 + e1;
            float zh = z0 + z1;
            sh += __shfl_xor_sync(0xffffffffu, sh, 16);   // combine K-halves
            eh += __shfl_xor_sync(0xffffffffu, eh, 16);
            zh += __shfl_xor_sync(0xffffffffu, zh, 16);

            const float h0v = fast_tanh(sh);
            float h1v = fast_tanh(eh);          // = h1_{i-1}
            if (i == 0) h1v = 0.f;              // h1_{-1} := 0
            const float zv = fmaxf(zh, 0.f);    // = z_{i-2}

            if (lead) {
                h0sm[bl][p ^ 1][j] = h0v;
                h1sm[bl][p ^ 1][j] = h1v;
                if (i >= 2) zb[(i - 2) * 64 + j] = zv;
                xsm[bl][(i + 8) & 15][j] = xreg[u];            // publish x_{i+8}
                if (i + 12 < T_) xreg[u] = xb[(i + 12) * 64 + j]; // fetch x_{i+12}
            }
            NAMED_BAR(barid, 128);
            p ^= 1;
        }
    }

    // Epilogue step 1: h1_{T-1} and z_{T-2}
    {
        unsigned long long c0 = pack2(bias1g, 0.f), c1 = 0ull;
        unsigned long long d0 = 0ull, d1 = 0ull;
        unsigned long long m0 = pack2(b1m, 0.f), m1 = 0ull;
        const ulonglong2* hp0 = (const ulonglong2*)&h0sm[bl][p][kh * 32];
        const ulonglong2* hp1 = (const ulonglong2*)&h1sm[bl][p][kh * 32];
#pragma unroll
        for (int m = 0; m < 16; m += 2) {
            ulonglong2 v = hp0[m >> 1];   // h0_{T-1}
            ulonglong2 g = hp1[m >> 1];   // h1_{T-2}
            c0 = fma2(wx[m],     v.x, c0);
            c1 = fma2(wx[m + 1], v.y, c1);
            d0 = fma2(w1[m],     g.x, d0);
            d1 = fma2(w1[m + 1], g.y, d1);
            m0 = fma2(wm[m],     g.x, m0);
            m1 = fma2(wm[m + 1], g.y, m1);
        }
        float e0, e1, z0, z1;
        unpack2(add2(add2(c0, c1), add2(d0, d1)), e0, e1);
        unpack2(add2(m0, m1), z0, z1);
        float eh = e0 + e1;
        float zh = z0 + z1;
        eh += __shfl_xor_sync(0xffffffffu, eh, 16);
        zh += __shfl_xor_sync(0xffffffffu, zh, 16);
        if (lead) {
            zb[(T_ - 2) * 64 + j] = fmaxf(zh, 0.f);
            h1sm[bl][p ^ 1][j] = fast_tanh(eh);   // h1_{T-1}
        }
        NAMED_BAR(barid, 128);
    }
    // Epilogue step 2: z_{T-1} = relu(W1 h1_{T-1} + b1)
    {
        unsigned long long m0 = pack2(b1m, 0.f), m1 = 0ull;
        const ulonglong2* hp1 = (const ulonglong2*)&h1sm[bl][p ^ 1][kh * 32];
#pragma unroll
        for (int m = 0; m < 16; m += 2) {
            ulonglong2 g = hp1[m >> 1];
            m0 = fma2(wm[m],     g.x, m0);
            m1 = fma2(wm[m + 1], g.y, m1);
        }
        float z0, z1;
        unpack2(add2(m0, m1), z0, z1);
        float zh = z0 + z1;
        zh += __shfl_xor_sync(0xffffffffu, zh, 16);
        if (lead) zb[(T_ - 1) * 64 + j] = fmaxf(zh, 0.f);
    }
}

// ============================================================================
// w2: out[r][o] = sum_j W2[o][j] z[r][j] + b2[o]  (O=2). 8 rows/iter (MLP).
// ============================================================================
__global__ void __launch_bounds__(128) w2_kernel(
    const float* __restrict__ z, const float* __restrict__ W2,
    const float* __restrict__ b2, float* __restrict__ out, int nrows)
{
    const int l = threadIdx.x & 31;
    const int wrp = threadIdx.x >> 5;
    const unsigned long long* Zu  = (const unsigned long long*)z;
    const unsigned long long* W2u = (const unsigned long long*)W2;

    const unsigned long long w2a = W2u[l];        // (W2[0][2l], W2[0][2l+1])
    const unsigned long long w2b = W2u[32 + l];   // (W2[1][2l], W2[1][2l+1])
    const float b20 = b2[0], b21 = b2[1];

    const int  warpId = blockIdx.x * 4 + wrp;
    const int  nw     = gridDim.x * 4;
    const long stride = 8L * nw;

    for (long r = 8L * warpId; r < nrows; r += stride) {
        unsigned long long zv[8];
#pragma unroll
        for (int q = 0; q < 8; q++)
            zv[q] = (r + q < nrows) ? Zu[(r + q) * 32 + l] : 0ull;

        float p0[8], p1[8];
#pragma unroll
        for (int q = 0; q < 8; q++) {
            float a0, a1, c0, c1;
            unpack2(fma2(w2a, zv[q], 0ull), a0, a1);
            unpack2(fma2(w2b, zv[q], 0ull), c0, c1);
            p0[q] = a0 + a1;
            p1[q] = c0 + c1;
        }
#pragma unroll
        for (int off = 16; off; off >>= 1) {
#pragma unroll
            for (int q = 0; q < 8; q++) {
                p0[q] += __shfl_xor_sync(0xffffffffu, p0[q], off);
                p1[q] += __shfl_xor_sync(0xffffffffu, p1[q], off);
            }
        }
        if (l == 0) {
#pragma unroll
            for (int q = 0; q < 8; q++)
                if (r + q < nrows)
                    *reinterpret_cast<float2*>(&out[(r + q) * 2]) =
                        make_float2(p0[q] + b20, p1[q] + b21);
        }
    }
}

// ============================================================================
extern "C" void kernel_launch(void* const* d_in, const int* in_sizes, int n_in,
                              void* d_out, int out_size)
{
    const float* x     = (const float*)d_in[0];
    const float* W_ih0 = (const float*)d_in[1];
    const float* W_hh0 = (const float*)d_in[2];
    const float* b_ih0 = (const float*)d_in[3];
    const float* b_hh0 = (const float*)d_in[4];
    const float* W_ih1 = (const float*)d_in[5];
    const float* W_hh1 = (const float*)d_in[6];
    const float* b_ih1 = (const float*)d_in[7];
    const float* b_hh1 = (const float*)d_in[8];
    const float* W1    = (const float*)d_in[9];
    const float* b1    = (const float*)d_in[10];
    const float* W2    = (const float*)d_in[11];
    const float* b2    = (const float*)d_in[12];
    float* out = (float*)d_out;

    static float* bufB = nullptr;
    if (!bufB) cudaGetSymbolAddress((void**)&bufB, g_bufB);

    // layer-0 projection + both RNN layers + MLP W1, all in one scan -> z
    fused_scan_kernel<<<B_ / 2, 256>>>(x, W_ih0, W_hh0, b_ih0, b_hh0,
                                       W_ih1, W_hh1, b_ih1, b_hh1,
                                       W1, b1, bufB);
    // out = z W2^T + b2
    w2_kernel<<<1024, 128>>>(bufB, W2, b2, out, NROWS);
}

// round 12
// speedup vs baseline: 1.3268x; 1.0711x over previous
#include <cuda_runtime.h>

#define B_  256
#define T_  2048
#define H_  64
#define O_  2
#define NROWS (B_ * T_)
#define PF  4   // fused-scan xin prefetch depth (T_ % PF == 0)

// Scratch (device globals — no allocation allowed in kernel_launch)
__device__ float g_bufA[NROWS * H_];
__device__ float g_bufB[NROWS * H_];

// ---------- packed f32x2 helpers (sm_103a FFMA2 path) ----------
static __device__ __forceinline__ unsigned long long pack2(float lo, float hi) {
    unsigned long long r;
    asm("mov.b64 %0, {%1, %2};" : "=l"(r) : "f"(lo), "f"(hi));
    return r;
}
static __device__ __forceinline__ void unpack2(unsigned long long v, float& a, float& b) {
    asm("mov.b64 {%0, %1}, %2;" : "=f"(a), "=f"(b) : "l"(v));
}
static __device__ __forceinline__ unsigned long long fma2(unsigned long long a,
                                                          unsigned long long b,
                                                          unsigned long long c) {
    unsigned long long d;
    asm("fma.rn.f32x2 %0, %1, %2, %3;" : "=l"(d) : "l"(a), "l"(b), "l"(c));
    return d;
}
static __device__ __forceinline__ unsigned long long add2(unsigned long long a,
                                                          unsigned long long b) {
    unsigned long long d;
    asm("add.rn.f32x2 %0, %1, %2;" : "=l"(d) : "l"(a), "l"(b));
    return d;
}

// Fast tanh, rel err ~1e-7, saturates correctly.
static __device__ __forceinline__ float fast_tanh(float x) {
    float e = __expf(2.0f * x);
    return 1.0f - __fdividef(2.0f, e + 1.0f);
}

#define NAMED_BAR(id, cnt) asm volatile("bar.sync %0, %1;" :: "r"(id), "r"(cnt) : "memory")

// ============================================================================
// gemm64 (4-row): out[r][j] = sum_k in[r][k]*W[j][k] + ba[j] + bb[j]
// Warp handles 4 rows/iter, both output halves. 4 outstanding row loads.
// (R9 config: measured 139 us.)
// ============================================================================
__global__ void __launch_bounds__(128) gemm64_kernel(
    const float* __restrict__ in, const float* __restrict__ W,
    const float* __restrict__ ba, const float* __restrict__ bb,
    float* __restrict__ out, int nrows)
{
    __shared__ __align__(16) unsigned long long xsm[4][2][4][32]; // [warp][buf][row][pair]
    const int l   = threadIdx.x & 31;
    const int wrp = threadIdx.x >> 5;
    const unsigned long long* Wu = (const unsigned long long*)W;
    const unsigned long long* Iu = (const unsigned long long*)in;

    unsigned long long wl[32], wh[32];
#pragma unroll
    for (int k = 0; k < 32; k++) {
        wl[k] = Wu[l * 32 + k];
        wh[k] = Wu[(l + 32) * 32 + k];
    }
    const float biasl = ba[l] + bb[l];
    const float biash = ba[l + 32] + bb[l + 32];

    const int  warpId = blockIdx.x * 4 + wrp;
    const int  nw     = gridDim.x * 4;
    const long stride = 4L * nw;

    long r = 4L * warpId;
    if (r >= nrows) return;
    unsigned long long xv[4];
#pragma unroll
    for (int q = 0; q < 4; q++)
        xv[q] = (r + q < nrows) ? Iu[(r + q) * 32 + l] : 0ull;
    int buf = 0;

    while (r < nrows) {
#pragma unroll
        for (int q = 0; q < 4; q++) xsm[wrp][buf][q][l] = xv[q];
        __syncwarp();

        long rn = r + stride;
        if (rn < nrows) {
#pragma unroll
            for (int q = 0; q < 4; q++)
                xv[q] = (rn + q < nrows) ? Iu[(rn + q) * 32 + l] : 0ull;
        }

        unsigned long long aL[4], aH[4], bL[4], bH[4];
#pragma unroll
        for (int q = 0; q < 4; q++) {
            aL[q] = pack2(biasl, 0.f); bL[q] = 0ull;
            aH[q] = pack2(biash, 0.f); bH[q] = 0ull;
        }
#pragma unroll
        for (int k = 0; k < 32; k += 2) {
#pragma unroll
            for (int q = 0; q < 4; q++) {
                ulonglong2 v = ((const ulonglong2*)&xsm[wrp][buf][q][0])[k >> 1];
                aL[q] = fma2(wl[k],     v.x, aL[q]);
                bL[q] = fma2(wl[k + 1], v.y, bL[q]);
                aH[q] = fma2(wh[k],     v.x, aH[q]);
                bH[q] = fma2(wh[k + 1], v.y, bH[q]);
            }
        }
#pragma unroll
        for (int q = 0; q < 4; q++) {
            if (r + q < nrows) {
                float s0, s1, t0, t1;
                unpack2(add2(aL[q], bL[q]), s0, s1);
                unpack2(add2(aH[q], bH[q]), t0, t1);
                out[(r + q) * 64 + l]      = s0 + s1;
                out[(r + q) * 64 + 32 + l] = t0 + t1;
            }
        }

        buf ^= 1;
        r = rn;
    }
}

// ============================================================================
// fused_scan + MLP-W1 (R9 config, measured ~740 us):
//   h0_i     = tanh(xin0_i + W_hh0 h0_{i-1})
//   h1_{i-1} = tanh(W_ih1 h0_{i-1} + b1rnn + W_hh1 h1_{i-2})
//   z_{i-2}  = relu(W1 h1_{i-2} + b1mlp)       <- reuses the h1_{i-2} loads
// Block = 256 thr = 2 batches x 4 warps; per-batch named barrier.
// Lane owns output j = wq*16+(l&15), K-half kh=l>>4; halves via shfl_xor(16).
// ============================================================================
__global__ void __launch_bounds__(256) fused_scan_kernel(
    const float* __restrict__ xin0,
    const float* __restrict__ Whh0, const float* __restrict__ Wih1,
    const float* __restrict__ Whh1,
    const float* __restrict__ b_ih1, const float* __restrict__ b_hh1,
    const float* __restrict__ W1,   const float* __restrict__ b1,
    float* __restrict__ zout)
{
    __shared__ __align__(16) float h0sm[2][2][64];
    __shared__ __align__(16) float h1sm[2][2][64];
    const int l     = threadIdx.x & 31;
    const int wid   = threadIdx.x >> 5;
    const int bl    = wid >> 2;            // batch slot (0..1)
    const int wq    = wid & 3;             // warp-in-batch
    const int j     = wq * 16 + (l & 15);  // owned output
    const int kh    = l >> 4;              // K-half
    const bool lead = (l < 16);
    const long b    = blockIdx.x * 2 + bl;
    const int barid = bl + 1;

    const unsigned long long* W0u = (const unsigned long long*)Whh0;
    const unsigned long long* Wxu = (const unsigned long long*)Wih1;
    const unsigned long long* W1u = (const unsigned long long*)Whh1;
    const unsigned long long* Wmu = (const unsigned long long*)W1;
    unsigned long long w0[16], wx[16], w1[16], wm[16];
#pragma unroll
    for (int m = 0; m < 16; m++) {
        const int k = kh * 16 + m;
        w0[m] = W0u[j * 32 + k];
        wx[m] = Wxu[j * 32 + k];
        w1[m] = W1u[j * 32 + k];
        wm[m] = Wmu[j * 32 + k];
    }
    const float bias1g = lead ? (b_ih1[j] + b_hh1[j]) : 0.f;
    const float b1m    = lead ? b1[j] : 0.f;

    if (lead) {
        h0sm[bl][0][j] = 0.f;   // h0_{-1}
        h1sm[bl][0][j] = 0.f;   // h1_{-2}
    }

    const float* xb = xin0 + b * T_ * 64;
    float*       zb = zout + b * T_ * 64;

    float xs[PF];
#pragma unroll
    for (int s = 0; s < PF; s++) xs[s] = xb[s * 64 + j];

    NAMED_BAR(barid, 128);

    int p = 0;
    for (int tb = 0; tb < T_; tb += PF) {
#pragma unroll
        for (int u = 0; u < PF; u++) {
            const int i = tb + u;
            const float xv = lead ? xs[u] : 0.f;
            if (i + PF < T_) xs[u] = xb[(i + PF) * 64 + j];

            // h0sm[bl][p] = h0_{i-1}, h1sm[bl][p] = h1_{i-2}
            unsigned long long a0 = pack2(xv, 0.f), a1 = 0ull;       // Whh0.h0
            unsigned long long c0 = pack2(bias1g, 0.f), c1 = 0ull;   // Wih1.h0
            unsigned long long d0 = 0ull, d1 = 0ull;                 // Whh1.h1
            unsigned long long m0 = pack2(b1m, 0.f), m1 = 0ull;      // W1.h1
            const ulonglong2* hp0 = (const ulonglong2*)&h0sm[bl][p][kh * 32];
            const ulonglong2* hp1 = (const ulonglong2*)&h1sm[bl][p][kh * 32];
#pragma unroll
            for (int m = 0; m < 16; m += 2) {
                ulonglong2 v = hp0[m >> 1];   // h0_{i-1}: one load, two uses
                ulonglong2 g = hp1[m >> 1];   // h1_{i-2}: one load, two uses
                a0 = fma2(w0[m],     v.x, a0);
                a1 = fma2(w0[m + 1], v.y, a1);
                c0 = fma2(wx[m],     v.x, c0);
                c1 = fma2(wx[m + 1], v.y, c1);
                d0 = fma2(w1[m],     g.x, d0);
                d1 = fma2(w1[m + 1], g.y, d1);
                m0 = fma2(wm[m],     g.x, m0);
                m1 = fma2(wm[m + 1], g.y, m1);
            }
            float s0, s1, e0, e1, z0, z1;
            unpack2(add2(a0, a1), s0, s1);
            unpack2(add2(add2(c0, c1), add2(d0, d1)), e0, e1);
            unpack2(add2(m0, m1), z0, z1);
            float sh = s0 + s1;
            float eh = e0 + e1;
            float zh = z0 + z1;
            sh += __shfl_xor_sync(0xffffffffu, sh, 16);   // combine K-halves
            eh += __shfl_xor_sync(0xffffffffu, eh, 16);
            zh += __shfl_xor_sync(0xffffffffu, zh, 16);

            const float h0v = fast_tanh(sh);
            float h1v = fast_tanh(eh);          // = h1_{i-1}
            if (i == 0) h1v = 0.f;              // h1_{-1} := 0
            const float zv = fmaxf(zh, 0.f);    // = z_{i-2}

            if (lead) {
                h0sm[bl][p ^ 1][j] = h0v;
                h1sm[bl][p ^ 1][j] = h1v;
                if (i >= 2) zb[(i - 2) * 64 + j] = zv;
            }
            NAMED_BAR(barid, 128);
            p ^= 1;
        }
    }

    // Epilogue step 1: h1_{T-1} and z_{T-2}
    {
        unsigned long long c0 = pack2(bias1g, 0.f), c1 = 0ull;
        unsigned long long d0 = 0ull, d1 = 0ull;
        unsigned long long m0 = pack2(b1m, 0.f), m1 = 0ull;
        const ulonglong2* hp0 = (const ulonglong2*)&h0sm[bl][p][kh * 32];
        const ulonglong2* hp1 = (const ulonglong2*)&h1sm[bl][p][kh * 32];
#pragma unroll
        for (int m = 0; m < 16; m += 2) {
            ulonglong2 v = hp0[m >> 1];   // h0_{T-1}
            ulonglong2 g = hp1[m >> 1];   // h1_{T-2}
            c0 = fma2(wx[m],     v.x, c0);
            c1 = fma2(wx[m + 1], v.y, c1);
            d0 = fma2(w1[m],     g.x, d0);
            d1 = fma2(w1[m + 1], g.y, d1);
            m0 = fma2(wm[m],     g.x, m0);
            m1 = fma2(wm[m + 1], g.y, m1);
        }
        float e0, e1, z0, z1;
        unpack2(add2(add2(c0, c1), add2(d0, d1)), e0, e1);
        unpack2(add2(m0, m1), z0, z1);
        float eh = e0 + e1;
        float zh = z0 + z1;
        eh += __shfl_xor_sync(0xffffffffu, eh, 16);
        zh += __shfl_xor_sync(0xffffffffu, zh, 16);
        if (lead) {
            zb[(T_ - 2) * 64 + j] = fmaxf(zh, 0.f);
            h1sm[bl][p ^ 1][j] = fast_tanh(eh);   // h1_{T-1}
        }
        NAMED_BAR(barid, 128);
    }
    // Epilogue step 2: z_{T-1} = relu(W1 h1_{T-1} + b1)
    {
        unsigned long long m0 = pack2(b1m, 0.f), m1 = 0ull;
        const ulonglong2* hp1 = (const ulonglong2*)&h1sm[bl][p ^ 1][kh * 32];
#pragma unroll
        for (int m = 0; m < 16; m += 2) {
            ulonglong2 g = hp1[m >> 1];
            m0 = fma2(wm[m],     g.x, m0);
            m1 = fma2(wm[m + 1], g.y, m1);
        }
        float z0, z1;
        unpack2(add2(m0, m1), z0, z1);
        float zh = z0 + z1;
        zh += __shfl_xor_sync(0xffffffffu, zh, 16);
        if (lead) zb[(T_ - 1) * 64 + j] = fmaxf(zh, 0.f);
    }
}

// ============================================================================
// w2: out[r][o] = sum_j W2[o][j] z[r][j] + b2[o]  (O=2). 8 rows/iter.
// (R11 config: measured 34.7 us, 4 TB/s.)
// ============================================================================
__global__ void __launch_bounds__(128) w2_kernel(
    const float* __restrict__ z, const float* __restrict__ W2,
    const float* __restrict__ b2, float* __restrict__ out, int nrows)
{
    const int l = threadIdx.x & 31;
    const int wrp = threadIdx.x >> 5;
    const unsigned long long* Zu  = (const unsigned long long*)z;
    const unsigned long long* W2u = (const unsigned long long*)W2;

    const unsigned long long w2a = W2u[l];        // (W2[0][2l], W2[0][2l+1])
    const unsigned long long w2b = W2u[32 + l];   // (W2[1][2l], W2[1][2l+1])
    const float b20 = b2[0], b21 = b2[1];

    const int  warpId = blockIdx.x * 4 + wrp;
    const int  nw     = gridDim.x * 4;
    const long stride = 8L * nw;

    for (long r = 8L * warpId; r < nrows; r += stride) {
        unsigned long long zv[8];
#pragma unroll
        for (int q = 0; q < 8; q++)
            zv[q] = (r + q < nrows) ? Zu[(r + q) * 32 + l] : 0ull;

        float p0[8], p1[8];
#pragma unroll
        for (int q = 0; q < 8; q++) {
            float a0, a1, c0, c1;
            unpack2(fma2(w2a, zv[q], 0ull), a0, a1);
            unpack2(fma2(w2b, zv[q], 0ull), c0, c1);
            p0[q] = a0 + a1;
            p1[q] = c0 + c1;
        }
#pragma unroll
        for (int off = 16; off; off >>= 1) {
#pragma unroll
            for (int q = 0; q < 8; q++) {
                p0[q] += __shfl_xor_sync(0xffffffffu, p0[q], off);
                p1[q] += __shfl_xor_sync(0xffffffffu, p1[q], off);
            }
        }
        if (l == 0) {
#pragma unroll
            for (int q = 0; q < 8; q++)
                if (r + q < nrows)
                    *reinterpret_cast<float2*>(&out[(r + q) * 2]) =
                        make_float2(p0[q] + b20, p1[q] + b21);
        }
    }
}

// ============================================================================
extern "C" void kernel_launch(void* const* d_in, const int* in_sizes, int n_in,
                              void* d_out, int out_size)
{
    const float* x     = (const float*)d_in[0];
    const float* W_ih0 = (const float*)d_in[1];
    const float* W_hh0 = (const float*)d_in[2];
    const float* b_ih0 = (const float*)d_in[3];
    const float* b_hh0 = (const float*)d_in[4];
    const float* W_ih1 = (const float*)d_in[5];
    const float* W_hh1 = (const float*)d_in[6];
    const float* b_ih1 = (const float*)d_in[7];
    const float* b_hh1 = (const float*)d_in[8];
    const float* W1    = (const float*)d_in[9];
    const float* b1    = (const float*)d_in[10];
    const float* W2    = (const float*)d_in[11];
    const float* b2    = (const float*)d_in[12];
    float* out = (float*)d_out;

    static float* bufA = nullptr;
    static float* bufB = nullptr;
    if (!bufA) {
        cudaGetSymbolAddress((void**)&bufA, g_bufA);
        cudaGetSymbolAddress((void**)&bufB, g_bufB);
    }

    // xin0 = x W_ih0^T + b_ih0 + b_hh0
    gemm64_kernel<<<1184, 128>>>(x, W_ih0, b_ih0, b_hh0, bufA, NROWS);
    // both RNN layers + MLP W1 -> z
    fused_scan_kernel<<<B_ / 2, 256>>>(bufA, W_hh0, W_ih1, W_hh1,
                                       b_ih1, b_hh1, W1, b1, bufB);
    // out = z W2^T + b2
    w2_kernel<<<1024, 128>>>(bufB, W2, b2, out, NROWS);
}